// round 17
// baseline (speedup 1.0000x reference)
#include <cuda_runtime.h>
#include <cuda_fp16.h>
#include <math.h>
#include <stdint.h>

#define Bb 16
#define Ss 4096
#define Dd 64
#define Hh 8
#define NB 64          // buckets per hash
#define NCHUNK 512     // Hh * NB
#define NEGV (-50000.0f)

typedef unsigned long long ull;
typedef unsigned int uint;

// ---------------- f32x2 packed-math helpers (sm_103a) -----------------------
__device__ __forceinline__ ull ffma2(ull a, ull b, ull c) {
    ull d;
    asm("fma.rn.f32x2 %0, %1, %2, %3;" : "=l"(d) : "l"(a), "l"(b), "l"(c));
    return d;
}
__device__ __forceinline__ ull pack2(float lo, float hi) {
    ull r;
    asm("mov.b64 %0, {%1, %2};" : "=l"(r) : "f"(lo), "f"(hi));
    return r;
}
__device__ __forceinline__ void unpack2(ull v, float& lo, float& hi) {
    asm("mov.b64 {%0, %1}, %2;" : "=f"(lo), "=f"(hi) : "l"(v));
}
__device__ __forceinline__ ull ld64s(const float* p) {
    return *(const ull*)p;
}

// ---------------- mma helpers -------------------------------------------------
__device__ __forceinline__ void mma_f16(float* c,
    uint a0, uint a1, uint a2, uint a3, uint b0, uint b1)
{
    asm("mma.sync.aligned.m16n8k16.row.col.f32.f16.f16.f32 "
        "{%0,%1,%2,%3}, {%4,%5,%6,%7}, {%8,%9}, {%0,%1,%2,%3};"
        : "+f"(c[0]), "+f"(c[1]), "+f"(c[2]), "+f"(c[3])
        : "r"(a0), "r"(a1), "r"(a2), "r"(a3), "r"(b0), "r"(b1));
}
// pack two f32 -> f16x2 word: lower half = 'lo' (even k), upper half = 'hi'
__device__ __forceinline__ uint pack_f16x2(float lo, float hi) {
    __half2 h = __floats2half2_rn(lo, hi);
    return *(uint*)&h;
}
__device__ __forceinline__ uint hmul2u(uint a, uint b) {
    __half2 r = __hmul2(*(__half2*)&a, *(__half2*)&b);
    return *(uint*)&r;
}

// ---------------- device scratch ---------------------------------------------
__device__ int   g_bucket[Bb*Hh*Ss];
__device__ int   g_perm  [Bb*Hh*Ss];
__device__ uint  g_o16 [(size_t)Bb*Hh*Ss*(Dd/2)];   // per-hash outputs, fp16x2
__device__ float g_logits[Bb*Hh*Ss];
__device__ uint  g_kn16[(size_t)Bb*Ss*(Dd/2)];      // normalized K-hat, fp16x2
__device__ uint  g_v16 [(size_t)Bb*Ss*(Dd/2)];      // V, fp16x2
__device__ float g_qs  [Bb*Ss];                     // (||q||+eps)*0.125

// ---------------- 0) per-token prep: normalize + fp16 conversion (once) ------
__global__ void __launch_bounds__(256) prep_kernel(
    const float* __restrict__ qk, const float* __restrict__ v)
{
    int tid = threadIdx.x;
    int q4  = tid & 15;
    size_t row = (size_t)blockIdx.x*16 + (tid >> 4);
    int c0 = q4*4;

    float4 xq = *(const float4*)(qk + row*Dd + c0);
    float4 xv = *(const float4*)(v  + row*Dd + c0);

    float ss = xq.x*xq.x + xq.y*xq.y + xq.z*xq.z + xq.w*xq.w;
    #pragma unroll
    for (int s = 1; s < 16; s <<= 1)
        ss += __shfl_xor_sync(0xffffffffu, ss, s, 16);
    float n = sqrtf(ss) + 1e-6f;
    float i = 1.0f / n;

    uint* kn = g_kn16 + row*(Dd/2) + q4*2;
    kn[0] = pack_f16x2(xq.x*i, xq.y*i);
    kn[1] = pack_f16x2(xq.z*i, xq.w*i);
    uint* vo = g_v16 + row*(Dd/2) + q4*2;
    vo[0] = pack_f16x2(xv.x, xv.y);
    vo[1] = pack_f16x2(xv.z, xv.w);
    if (q4 == 0) g_qs[row] = n * 0.125f;
}

// ---------------- 1) LSH hashing (bit-exact f-sequential accumulation) -------
#define TT 32
#define QT_STRIDE 34
__global__ void __launch_bounds__(256) hash_kernel(
    const float* __restrict__ qk, const float* __restrict__ rot,
    float* __restrict__ outb)
{
    __shared__ float qsT[64*QT_STRIDE];

    int blocksPerB = Ss / TT;                 // 128
    int b  = blockIdx.x / blocksPerB;
    int t0 = (blockIdx.x % blocksPerB) * TT;
    int tid = threadIdx.x;

    {
        int f = tid & 63;
        int i0 = tid >> 6;
        #pragma unroll
        for (int i = i0; i < TT; i += 4)
            qsT[f*QT_STRIDE + i] = qk[((size_t)b*Ss + t0 + i)*Dd + f];
    }
    __syncthreads();

    const float* rb = rot + (size_t)b*64*256 + tid;

    ull acc2[TT/2];
    #pragma unroll
    for (int ip = 0; ip < TT/2; ip++) acc2[ip] = 0ull;
    #pragma unroll 4
    for (int f = 0; f < 64; f++) {
        float rv = __ldg(rb + f*256);
        ull rv2 = pack2(rv, rv);
        #pragma unroll
        for (int ip = 0; ip < TT/2; ip++)
            acc2[ip] = ffma2(ld64s(qsT + f*QT_STRIDE + 2*ip), rv2, acc2[ip]);
    }

    int lane = tid & 31;
    int h    = tid >> 5;
    #pragma unroll
    for (int ip = 0; ip < TT/2; ip++) {
        float va[2];
        unpack2(acc2[ip], va[0], va[1]);
        #pragma unroll
        for (int s = 0; s < 2; s++) {
            float v = va[s];
            float val; int idx;
            if (v >= -v) { val = v;  idx = lane; }
            else         { val = -v; idx = lane + 32; }
            #pragma unroll
            for (int m = 16; m > 0; m >>= 1) {
                float ov = __shfl_xor_sync(0xffffffffu, val, m);
                int   oi = __shfl_xor_sync(0xffffffffu, idx, m);
                if (ov > val || (ov == val && oi < idx)) { val = ov; idx = oi; }
            }
            if (lane == 0) {
                int pos = ((size_t)b*Hh + h)*Ss + t0 + 2*ip + s;
                g_bucket[pos] = idx;
                if (outb) outb[pos] = (float)(idx + h*NB);
            }
        }
    }
}

// ---------------- 2) stable counting sort per (b,h), ballot-ranked ----------
__global__ void __launch_bounds__(256) sort_kernel()
{
    __shared__ int sb[Ss];
    __shared__ int cnt[NB];
    __shared__ int offs[NB + 1];
    int bh   = blockIdx.x;
    int tid  = threadIdx.x;
    int lane = tid & 31;
    int w    = tid >> 5;
    const int base = bh * Ss;

    if (tid < NB) cnt[tid] = 0;
    __syncthreads();
    for (int i = tid; i < Ss; i += 256) {
        int v = g_bucket[base + i];
        sb[i] = v;
        atomicAdd(&cnt[v], 1);
    }
    __syncthreads();
    if (tid == 0) {
        offs[0] = 0;
        for (int k = 0; k < NB; k++) offs[k+1] = offs[k] + cnt[k];
    }
    __syncthreads();

    int off[8];
    #pragma unroll
    for (int k = 0; k < 8; k++) off[k] = offs[8*w + k];

    for (int step = 0; step < Ss/32; step++) {
        int t   = step*32 + lane;
        int rel = sb[t] - 8*w;
        #pragma unroll
        for (int k = 0; k < 8; k++) {
            unsigned mask = __ballot_sync(0xffffffffu, rel == k);
            if (rel == k) {
                int pos = off[k] + __popc(mask & ((1u << lane) - 1u));
                g_perm[base + pos] = t;
            }
            off[k] += __popc(mask);
        }
    }
}

// ---------------- 3) chunked attention: fp16 QK/PV, 3 barriers --------------
// ks16[128][36w] : normalized K fp16x2 (rows 0..63 = Q)
// ph2[64][68w]   : RAW e = exp(d - m_half) as fp16x2 (separate buffer)
// vhw[64][68w]   : V fp16 transposed [col][k-pair], XOR swizzled
#define KS16_LD 36
#define PH_LD 68
#define SM_KS16 0
#define SM_PH   (128*KS16_LD)           // 4608
#define SM_VH   (SM_PH + 64*PH_LD)      // 8960
#define SM_PM   (SM_VH + 64*68)         // 13312
#define SM_PS   (SM_PM + 128)
#define SM_QSC  (SM_PS + 128)
#define SM_TK   (SM_QSC + 64)
#define ATTN_SMEM ((SM_TK + 128) * 4)   // 55040 bytes
__global__ void __launch_bounds__(256, 4) attn_kernel()
{
    extern __shared__ float sm[];
    uint*  ks16 = (uint*)(sm + SM_KS16);
    uint*  ph2  = (uint*)(sm + SM_PH);
    uint*  vhw  = (uint*)(sm + SM_VH);
    float* pm   = sm + SM_PM;
    float* ps   = sm + SM_PS;
    float* qsc  = sm + SM_QSC;
    int*   tk   = (int*)(sm + SM_TK);

    int b = blockIdx.x >> 9;
    int c = blockIdx.x & (NCHUNK - 1);
    int h = c >> 6;
    int cprev = (c + NCHUNK - 1) & (NCHUNK - 1);
    int tid = threadIdx.x;
    const int pbase = b * (Hh * Ss);
    const size_t tokbase = (size_t)b*Ss;

    if (tid < 64)        tk[tid] = g_perm[pbase + c*64 + tid];
    else if (tid < 128)  tk[tid] = g_perm[pbase + cprev*64 + (tid - 64)];
    __syncthreads();

    // ---- gather: pure LDG -> (PRMT) -> STS; all math prehoisted ----
    {
        int q4 = tid & 15;
        int rp = tid >> 4;
        int kw = q4*2;
        if (tid < 64) qsc[tid] = g_qs[tokbase + tk[tid]];
        #pragma unroll
        for (int pp = 0; pp < 4; pp++) {
            int r0 = 32*pp + 2*rp, r1 = r0 + 1;
            size_t t0 = tokbase + tk[r0], t1 = tokbase + tk[r1];
            uint2 kn0 = *(const uint2*)(g_kn16 + t0*(Dd/2) + kw);
            uint2 kn1 = *(const uint2*)(g_kn16 + t1*(Dd/2) + kw);
            uint2 v0  = *(const uint2*)(g_v16  + t0*(Dd/2) + kw);
            uint2 v1  = *(const uint2*)(g_v16  + t1*(Dd/2) + kw);
            *(uint2*)(ks16 + r0*KS16_LD + kw) = kn0;
            *(uint2*)(ks16 + r1*KS16_LD + kw) = kn1;
            // V transpose repack: word (col e) = (v[r0][e], v[r1][e])
            int kp = r0 >> 1;
            int e0 = q4*4;
            vhw[(e0+0)*68 + (kp ^ ((e0+0) >> 2))] = __byte_perm(v0.x, v1.x, 0x5410);
            vhw[(e0+1)*68 + (kp ^ ((e0+1) >> 2))] = __byte_perm(v0.x, v1.x, 0x7632);
            vhw[(e0+2)*68 + (kp ^ ((e0+2) >> 2))] = __byte_perm(v0.y, v1.y, 0x5410);
            vhw[(e0+3)*68 + (kp ^ ((e0+3) >> 2))] = __byte_perm(v0.y, v1.y, 0x7632);
        }
    }
    __syncthreads();

    // ---- QK^T : 64x128x64 fp16 m16n8k16, per warp m16 x n64 ----
    int wid   = tid >> 5;
    int lane  = tid & 31;
    int gr    = lane >> 2;
    int cl    = lane & 3;
    int mrow  = 16*(wid & 3);
    int chalf = wid >> 2;
    int ncol  = 64*chalf;

    float acc[8][4];
    #pragma unroll
    for (int n = 0; n < 8; n++)
        #pragma unroll
        for (int i = 0; i < 4; i++) acc[n][i] = 0.f;

    {
        const uint* ar0 = ks16 + (mrow + gr)*KS16_LD;
        const uint* ar1 = ar0 + 8*KS16_LD;
        #pragma unroll
        for (int k0 = 0; k0 < 4; k0++) {
            int wa = 8*k0 + cl;
            uint a0 = ar0[wa], a1 = ar1[wa], a2 = ar0[wa+4], a3 = ar1[wa+4];
            #pragma unroll
            for (int n = 0; n < 8; n++) {
                const uint* bp = ks16 + (ncol + 8*n + gr)*KS16_LD;
                uint b0 = bp[wa], b1 = bp[wa+4];
                mma_f16(acc[n], a0, a1, a2, a3, b0, b1);
            }
        }
    }

    // ---- mask + scale + per-half softmax partials + RAW e write ----
    int row0 = mrow + gr, row1 = row0 + 8;
    int tr0 = tk[row0], tr1 = tk[row1];
    float sc0 = qsc[row0], sc1 = qsc[row1];
    float m0 = -1e30f, m1 = -1e30f;
    #pragma unroll
    for (int n = 0; n < 8; n++) {
        int j0 = ncol + 8*n + 2*cl;
        int tj0 = tk[j0], tj1 = tk[j0 + 1];
        float d0 = (tj0 == tr0) ? NEGV : acc[n][0]*sc0;
        float d1 = (tj1 == tr0) ? NEGV : acc[n][1]*sc0;
        float d2 = (tj0 == tr1) ? NEGV : acc[n][2]*sc1;
        float d3 = (tj1 == tr1) ? NEGV : acc[n][3]*sc1;
        acc[n][0] = d0; acc[n][1] = d1; acc[n][2] = d2; acc[n][3] = d3;
        m0 = fmaxf(m0, fmaxf(d0, d1));
        m1 = fmaxf(m1, fmaxf(d2, d3));
    }
    #pragma unroll
    for (int s = 1; s < 4; s <<= 1) {
        m0 = fmaxf(m0, __shfl_xor_sync(0xffffffffu, m0, s));
        m1 = fmaxf(m1, __shfl_xor_sync(0xffffffffu, m1, s));
    }
    float s0 = 0.f, s1 = 0.f;
    #pragma unroll
    for (int n = 0; n < 8; n++) {
        float e0 = __expf(acc[n][0] - m0);
        float e1 = __expf(acc[n][1] - m0);
        float e2 = __expf(acc[n][2] - m1);
        float e3 = __expf(acc[n][3] - m1);
        acc[n][0] = e0; acc[n][1] = e1; acc[n][2] = e2; acc[n][3] = e3;
        s0 += e0 + e1;
        s1 += e2 + e3;
    }
    #pragma unroll
    for (int s = 1; s < 4; s <<= 1) {
        s0 += __shfl_xor_sync(0xffffffffu, s0, s);
        s1 += __shfl_xor_sync(0xffffffffu, s1, s);
    }
    if (cl == 0) {
        pm[chalf*64 + row0] = m0;  ps[chalf*64 + row0] = s0;
        pm[chalf*64 + row1] = m1;  ps[chalf*64 + row1] = s1;
    }
    // raw e -> separate probs buffer (no lse dependency, no overlay race)
    {
        int pw0 = row0*PH_LD + (ncol >> 1) + cl;
        int pw1 = row1*PH_LD + (ncol >> 1) + cl;
        #pragma unroll
        for (int n = 0; n < 8; n++) {
            ph2[pw0 + 4*n] = pack_f16x2(acc[n][0], acc[n][1]);
            ph2[pw1 + 4*n] = pack_f16x2(acc[n][2], acc[n][3]);
        }
    }
    __syncthreads();   // single barrier: partials + raw probs visible

    // ---- lse + scale factors ----
    float Ma0 = pm[row0], Mb0 = pm[64 + row0];
    float M0  = fmaxf(Ma0, Mb0);
    float S0  = ps[row0]*__expf(Ma0 - M0) + ps[64 + row0]*__expf(Mb0 - M0);
    float lse0 = M0 + __logf(S0);
    float Ma1 = pm[row1], Mb1 = pm[64 + row1];
    float M1  = fmaxf(Ma1, Mb1);
    float S1  = ps[row1]*__expf(Ma1 - M1) + ps[64 + row1]*__expf(Mb1 - M1);
    float lse1 = M1 + __logf(S1);

    if (cl == 0 && chalf == 0) {
        g_logits[pbase + h*Ss + tr0] = lse0;
        g_logits[pbase + h*Ss + tr1] = lse1;
    }

    int otherhalf = 1 - chalf;
    float fo0 = __expf(m0 - lse0);                       // own-half factors
    float fo1 = __expf(m1 - lse1);
    float fc0 = __expf(pm[otherhalf*64 + row0] - lse0);  // cross-half factors
    float fc1 = __expf(pm[otherhalf*64 + row1] - lse1);
    uint fc0x2 = pack_f16x2(fc0, fc0);
    uint fc1x2 = pack_f16x2(fc1, fc1);

    // own-half A fragments straight from registers (scaled by fo)
    uint aA[4][4];
    #pragma unroll
    for (int lc = 0; lc < 4; lc++) {
        int n = 2*lc;
        aA[lc][0] = pack_f16x2(acc[n][0]*fo0,   acc[n][1]*fo0);
        aA[lc][1] = pack_f16x2(acc[n][2]*fo1,   acc[n][3]*fo1);
        aA[lc][2] = pack_f16x2(acc[n+1][0]*fo0, acc[n+1][1]*fo0);
        aA[lc][3] = pack_f16x2(acc[n+1][2]*fo1, acc[n+1][3]*fo1);
    }

    // ---- PV : 64x64x128 fp16, m16n8k16, per warp m16 x n32 ----
    int ocol = 32*chalf;
    float oacc[4][4];
    #pragma unroll
    for (int n = 0; n < 4; n++)
        #pragma unroll
        for (int i = 0; i < 4; i++) oacc[n][i] = 0.f;

    int ebase[4], sxor[4];
    #pragma unroll
    for (int n = 0; n < 4; n++) {
        int e = ocol + 8*n + gr;
        ebase[n] = e*68;
        sxor[n]  = e >> 2;
    }
    const uint* ph2r0 = ph2 + row0*PH_LD;
    const uint* ph2r1 = ph2 + row1*PH_LD;

    // cross-half k chunks: A from smem (raw e), scaled by fc
    #pragma unroll
    for (int lc = 0; lc < 4; lc++) {
        int k0 = 4*otherhalf + lc;
        int wa = 8*k0 + cl;
        uint a0 = hmul2u(ph2r0[wa],   fc0x2);
        uint a1 = hmul2u(ph2r1[wa],   fc1x2);
        uint a2 = hmul2u(ph2r0[wa+4], fc0x2);
        uint a3 = hmul2u(ph2r1[wa+4], fc1x2);
        #pragma unroll
        for (int n = 0; n < 4; n++) {
            uint bh0 = vhw[ebase[n] + (wa ^ sxor[n])];
            uint bh1 = vhw[ebase[n] + ((wa + 4) ^ sxor[n])];
            mma_f16(oacc[n], a0, a1, a2, a3, bh0, bh1);
        }
    }
    // own-half k chunks: A from registers
    #pragma unroll
    for (int lc = 0; lc < 4; lc++) {
        int k0 = 4*chalf + lc;
        int wa = 8*k0 + cl;
        #pragma unroll
        for (int n = 0; n < 4; n++) {
            uint bh0 = vhw[ebase[n] + (wa ^ sxor[n])];
            uint bh1 = vhw[ebase[n] + ((wa + 4) ^ sxor[n])];
            mma_f16(oacc[n], aA[lc][0], aA[lc][1], aA[lc][2], aA[lc][3], bh0, bh1);
        }
    }

    // ---- scatter to g_o16 (fp16x2) ----
    {
        uint* orow0 = g_o16 + (size_t)(pbase + h*Ss + tr0)*(Dd/2);
        uint* orow1 = g_o16 + (size_t)(pbase + h*Ss + tr1)*(Dd/2);
        #pragma unroll
        for (int n = 0; n < 4; n++) {
            int wcol = (ocol >> 1) + 4*n + cl;
            orow0[wcol] = pack_f16x2(oacc[n][0], oacc[n][1]);
            orow1[wcol] = pack_f16x2(oacc[n][2], oacc[n][3]);
        }
    }
}

// ---------------- 4) combine hash rounds via softmax(logits) ----------------
__global__ void __launch_bounds__(256) combine_kernel(float* __restrict__ out)
{
    size_t gid = (size_t)blockIdx.x*256 + threadIdx.x;
    if (gid >= (size_t)Bb*Ss*Dd/8) return;
    int pair = (int)(gid & 7);
    size_t bt = gid >> 3;
    int t = (int)(bt & (Ss - 1));
    int b = (int)(bt >> 12);

    float l[Hh];
    float m = -1e30f;
    #pragma unroll
    for (int h = 0; h < Hh; h++) {
        l[h] = g_logits[((size_t)(b*Hh + h))*Ss + t];
        m = fmaxf(m, l[h]);
    }
    float ssum = 0.f;
    #pragma unroll
    for (int h = 0; h < Hh; h++) { l[h] = __expf(l[h] - m); ssum += l[h]; }
    float inv = 1.f / ssum;

    float4 acc0 = make_float4(0.f, 0.f, 0.f, 0.f);
    float4 acc1 = make_float4(0.f, 0.f, 0.f, 0.f);
    #pragma unroll
    for (int h = 0; h < Hh; h++) {
        float w = l[h]*inv;
        const uint4 ow = *(const uint4*)(g_o16 + (((size_t)(b*Hh + h))*Ss + t)*(Dd/2) + pair*4);
        float2 f0 = __half22float2(*(const __half2*)&ow.x);
        float2 f1 = __half22float2(*(const __half2*)&ow.y);
        float2 f2 = __half22float2(*(const __half2*)&ow.z);
        float2 f3 = __half22float2(*(const __half2*)&ow.w);
        acc0.x += w*f0.x; acc0.y += w*f0.y; acc0.z += w*f1.x; acc0.w += w*f1.y;
        acc1.x += w*f2.x; acc1.y += w*f2.y; acc1.z += w*f3.x; acc1.w += w*f3.y;
    }
    float* dst = out + bt*Dd + pair*8;
    *(float4*)(dst)     = acc0;
    *(float4*)(dst + 4) = acc1;
}

// ---------------- launch ------------------------------------------------------
extern "C" void kernel_launch(void* const* d_in, const int* in_sizes, int n_in,
                              void* d_out, int out_size)
{
    const float* qk  = (const float*)d_in[0];
    const float* v   = (const float*)d_in[1];
    const float* rot = (const float*)d_in[2];
    float* out = (float*)d_out;

    cudaFuncSetAttribute(attn_kernel, cudaFuncAttributeMaxDynamicSharedMemorySize, ATTN_SMEM);

    float* outb = (out_size >= Bb*Ss*Dd + Bb*Hh*Ss) ? (out + (size_t)Bb*Ss*Dd) : nullptr;

    prep_kernel<<<Bb*Ss/16, 256>>>(qk, v);
    hash_kernel<<<Bb*(Ss/TT), 256>>>(qk, rot, outb);
    sort_kernel<<<Bb*Hh, 256>>>();
    attn_kernel<<<Bb*NCHUNK, 256, ATTN_SMEM>>>();
    combine_kernel<<<(int)(((size_t)Bb*Ss*Dd/8 + 255)/256), 256>>>(out);
}